// round 13
// baseline (speedup 1.0000x reference)
#include <cuda_runtime.h>

// out[i] = floorf(image[i] * 0.5f) — HBM-bound streaming.
// Persistent single-wave grid-stride kernel: grid = 1216 blocks (~152 SMs x 8
// resident blocks) eliminates the ~5 wave transitions + tail of the 6144-block
// launch. Memory shape = best measured (R11): 256-bit v8 accesses,
// L2::evict_last loads + L2::evict_first stores, 2 front-batched loads/iter.

#define V8PT 2          // v8 (32B) vectors per loop iteration per thread
#define TPB  256
#define PERSISTENT_BLOCKS 1216   // ~152 SMs * 8 resident blocks

__device__ __forceinline__ void ld256_evict_last(const float* p, unsigned* v) {
    asm volatile("ld.global.L2::evict_last.v8.b32 {%0,%1,%2,%3,%4,%5,%6,%7}, [%8];"
                 : "=r"(v[0]), "=r"(v[1]), "=r"(v[2]), "=r"(v[3]),
                   "=r"(v[4]), "=r"(v[5]), "=r"(v[6]), "=r"(v[7])
                 : "l"(p));
}

__device__ __forceinline__ void st256_evict_first(float* p, const unsigned* v) {
    asm volatile("st.global.L2::evict_first.v8.b32 [%0], {%1,%2,%3,%4,%5,%6,%7,%8};"
                 :: "l"(p),
                    "r"(v[0]), "r"(v[1]), "r"(v[2]), "r"(v[3]),
                    "r"(v[4]), "r"(v[5]), "r"(v[6]), "r"(v[7])
                 : "memory");
}

__device__ __forceinline__ void halve8(unsigned* v) {
    #pragma unroll
    for (int j = 0; j < 8; j++) {
        float f = __uint_as_float(v[j]);
        v[j] = __float_as_uint(floorf(f * 0.5f));
    }
}

__global__ void __launch_bounds__(TPB) stego_halve_kernel(
    const float* __restrict__ in, float* __restrict__ out, int n8)
{
    const int chunk = TPB * V8PT;                 // v8 units per block-iteration
    const int gridStride = gridDim.x * chunk;
    int t = threadIdx.x;

    for (int blockBase = blockIdx.x * chunk; blockBase < n8; blockBase += gridStride) {
        if (blockBase + chunk <= n8) {
            unsigned v[V8PT][8];
            #pragma unroll
            for (int k = 0; k < V8PT; k++)
                ld256_evict_last(in + (size_t)(blockBase + t + k * TPB) * 8, v[k]);
            #pragma unroll
            for (int k = 0; k < V8PT; k++) {
                halve8(v[k]);
                st256_evict_first(out + (size_t)(blockBase + t + k * TPB) * 8, v[k]);
            }
        } else {
            #pragma unroll
            for (int k = 0; k < V8PT; k++) {
                int i = blockBase + t + k * TPB;
                if (i < n8) {
                    unsigned v[8];
                    ld256_evict_last(in + (size_t)i * 8, v);
                    halve8(v);
                    st256_evict_first(out + (size_t)i * 8, v);
                }
            }
        }
    }
}

extern "C" void kernel_launch(void* const* d_in, const int* in_sizes, int n_in,
                              void* d_out, int out_size)
{
    const float* img = (const float*)d_in[0];
    float* out = (float*)d_out;
    int n = in_sizes[0];                 // 25,165,824 — divisible by 8
    int n8 = n / 8;
    int chunk = TPB * V8PT;
    int blocksNeeded = (n8 + chunk - 1) / chunk;
    int blocks = blocksNeeded < PERSISTENT_BLOCKS ? blocksNeeded : PERSISTENT_BLOCKS;
    stego_halve_kernel<<<blocks, TPB>>>(img, out, n8);
}

// round 14
// speedup vs baseline: 1.0589x; 1.0589x over previous
#include <cuda_runtime.h>

// out[i] = floorf(image[i] * 0.5f) — HBM-bound streaming. FINAL CONFIG (R11):
// best of 9 measured variants (25.57us kernel @ 5566 GB/s, DRAM-ceiling-bound).
//   - flat grid 6144 x 256 (beats persistent grid-stride: keeps loads
//     front-batched, no loop-carried deps, 22 regs / 74-77% occ)
//   - 2 x 256-bit (v8.b32) accesses per thread, warp-coalesced (t + k*TPB)
//   - L2::evict_last loads + L2::evict_first stores (best-measured hint combo;
//     hints move <7% traffic but this pairing measured fastest)

#define V8PT 2  // 8-float (32B) vectors per thread
#define TPB  256

__device__ __forceinline__ void ld256_evict_last(const float* p, unsigned* v) {
    asm volatile("ld.global.L2::evict_last.v8.b32 {%0,%1,%2,%3,%4,%5,%6,%7}, [%8];"
                 : "=r"(v[0]), "=r"(v[1]), "=r"(v[2]), "=r"(v[3]),
                   "=r"(v[4]), "=r"(v[5]), "=r"(v[6]), "=r"(v[7])
                 : "l"(p));
}

__device__ __forceinline__ void st256_evict_first(float* p, const unsigned* v) {
    asm volatile("st.global.L2::evict_first.v8.b32 [%0], {%1,%2,%3,%4,%5,%6,%7,%8};"
                 :: "l"(p),
                    "r"(v[0]), "r"(v[1]), "r"(v[2]), "r"(v[3]),
                    "r"(v[4]), "r"(v[5]), "r"(v[6]), "r"(v[7])
                 : "memory");
}

__device__ __forceinline__ void halve8(unsigned* v) {
    #pragma unroll
    for (int j = 0; j < 8; j++) {
        float f = __uint_as_float(v[j]);
        v[j] = __float_as_uint(floorf(f * 0.5f));
    }
}

__global__ void __launch_bounds__(TPB) stego_halve_kernel(
    const float* __restrict__ in, float* __restrict__ out, int n8)
{
    int blockBase = blockIdx.x * (TPB * V8PT);   // in v8 units
    int t = threadIdx.x;

    if (blockBase + TPB * V8PT <= n8) {
        unsigned v[V8PT][8];
        #pragma unroll
        for (int k = 0; k < V8PT; k++)
            ld256_evict_last(in + (size_t)(blockBase + t + k * TPB) * 8, v[k]);
        #pragma unroll
        for (int k = 0; k < V8PT; k++) {
            halve8(v[k]);
            st256_evict_first(out + (size_t)(blockBase + t + k * TPB) * 8, v[k]);
        }
    } else {
        // tail (unused for n = 25,165,824, but safe)
        #pragma unroll
        for (int k = 0; k < V8PT; k++) {
            int i = blockBase + t + k * TPB;
            if (i < n8) {
                unsigned v[8];
                ld256_evict_last(in + (size_t)i * 8, v);
                halve8(v);
                st256_evict_first(out + (size_t)i * 8, v);
            }
        }
    }
}

extern "C" void kernel_launch(void* const* d_in, const int* in_sizes, int n_in,
                              void* d_out, int out_size)
{
    const float* img = (const float*)d_in[0];
    float* out = (float*)d_out;
    int n = in_sizes[0];                 // 25,165,824 — divisible by 8
    int n8 = n / 8;
    int elems_per_block = TPB * V8PT;
    int blocks = (n8 + elems_per_block - 1) / elems_per_block;
    stego_halve_kernel<<<blocks, TPB>>>(img, out, n8);
}